// round 2
// baseline (speedup 1.0000x reference)
#include <cuda_runtime.h>
#include <stdint.h>

// Shapes (fixed by the problem)
#define BATCH 32
#define SEQ   4096
#define VOCAB 10
#define FEAT  1024
#define DIM   64

#define CHUNK   256     // l-tokens per block in the gather kernel
#define THREADS 256

// Precomputed projected table: P[d][v] = b[d] + sum_f fp[v][f] * W[d][f]
__device__ float g_P[DIM * VOCAB];

// ---------------------------------------------------------------------------
// Kernel 1: tiny 10x64x1024 GEMM. One warp per (d, v) pair -> 640 warps.
// fp_table (40 KB) and W (256 KB) are read coalesced; everything fits in L2.
// ---------------------------------------------------------------------------
__global__ void compute_P_kernel(const float* __restrict__ fp,
                                 const float* __restrict__ W,
                                 const float* __restrict__ bias) {
    int w    = (blockIdx.x * blockDim.x + threadIdx.x) >> 5;
    int lane = threadIdx.x & 31;
    if (w >= DIM * VOCAB) return;
    int d = w / VOCAB;
    int v = w - d * VOCAB;

    const float* fr = fp + v * FEAT;
    const float* wr = W  + d * FEAT;

    float s = 0.f;
#pragma unroll
    for (int f = lane; f < FEAT; f += 32)
        s += fr[f] * wr[f];

#pragma unroll
    for (int o = 16; o > 0; o >>= 1)
        s += __shfl_down_sync(0xffffffffu, s, o);

    if (lane == 0)
        g_P[d * VOCAB + v] = s + bias[d];
}

// ---------------------------------------------------------------------------
// Kernel 2: gather/scatter. out[(b*DIM + d)*SEQ + l] = P[d][idx[b][l]]
// One block per (b, l-chunk). Indices cached in smem as uint8; P cached in
// smem laid out [d][v] so a warp (fixed d) reads <=10 consecutive words
// (conflict-free broadcast). Writes are float4, lane-consecutive in l ->
// fully coalesced 128B transactions. Strictly HBM-store-bound.
// ---------------------------------------------------------------------------
__global__ void gather_kernel(const int* __restrict__ idx,
                              float* __restrict__ out) {
    __shared__ float         sP[DIM * VOCAB];
    __shared__ unsigned char sidx[CHUNK];

    const int b   = blockIdx.y;
    const int l0  = blockIdx.x * CHUNK;
    const int tid = threadIdx.x;

    // Load projected table into shared
    for (int i = tid; i < DIM * VOCAB; i += THREADS)
        sP[i] = g_P[i];

    // Load + compress this chunk's indices (values are 0..9)
    const int* ip = idx + b * SEQ + l0;
    for (int i = tid; i < CHUNK; i += THREADS)
        sidx[i] = (unsigned char)ip[i];

    __syncthreads();

    const int LQ = CHUNK / 4;                 // float4 groups per row chunk
    float* ob = out + (b * DIM) * SEQ + l0;

#pragma unroll 4
    for (int i = tid; i < DIM * LQ; i += THREADS) {
        int d  = i >> 6;                      // i / LQ  (LQ == 64)
        int lq = i & (LQ - 1);

        uint32_t v4 = *reinterpret_cast<const uint32_t*>(&sidx[lq * 4]);
        const float* p = &sP[d * VOCAB];

        float4 r;
        r.x = p[ v4        & 0xff];
        r.y = p[(v4 >> 8)  & 0xff];
        r.z = p[(v4 >> 16) & 0xff];
        r.w = p[ v4 >> 24        ];

        *reinterpret_cast<float4*>(ob + d * SEQ + lq * 4) = r;
    }
}

// ---------------------------------------------------------------------------
// Launch: two kernels on the same stream (graph-capturable, no allocs).
// Inputs per metadata order: indices (int32!), fp_table (f32), W (f32), b (f32)
// ---------------------------------------------------------------------------
extern "C" void kernel_launch(void* const* d_in, const int* in_sizes, int n_in,
                              void* d_out, int out_size) {
    const int*   idx  = (const int*)d_in[0];
    const float* fp   = (const float*)d_in[1];
    const float* W    = (const float*)d_in[2];
    const float* bias = (const float*)d_in[3];
    float*       out  = (float*)d_out;

    // 640 warps -> 80 blocks of 256 threads
    compute_P_kernel<<<80, 256>>>(fp, W, bias);

    dim3 grid(SEQ / CHUNK, BATCH);            // (16, 32) = 512 blocks
    gather_kernel<<<grid, THREADS>>>(idx, out);
}

// round 3
// speedup vs baseline: 1.0049x; 1.0049x over previous
#include <cuda_runtime.h>
#include <stdint.h>

// Shapes (fixed by the problem)
#define BATCH 32
#define SEQ   4096
#define VOCAB 10
#define FEAT  1024
#define DIM   64

#define CHUNK   256     // l-tokens per block in the gather kernel
#define THREADS 256
#define ITERS   (DIM * (CHUNK / 4) / THREADS)   // 16

// Precomputed projected table: P[d][v] = b[d] + sum_f fp[v][f] * W[d][f]
__device__ float g_P[DIM * VOCAB];

// ---------------------------------------------------------------------------
// Kernel 1: tiny 10x64x1024 GEMM. One warp per (d, v) pair -> 640 warps.
// float4 loads: 8 x LDG.128 per operand row -> deep MLP on the cold-read path.
// ---------------------------------------------------------------------------
__global__ void compute_P_kernel(const float* __restrict__ fp,
                                 const float* __restrict__ W,
                                 const float* __restrict__ bias) {
    int w    = (blockIdx.x * blockDim.x + threadIdx.x) >> 5;
    int lane = threadIdx.x & 31;
    if (w >= DIM * VOCAB) return;
    int d = w / VOCAB;
    int v = w - d * VOCAB;

    const float4* fr = reinterpret_cast<const float4*>(fp + v * FEAT);
    const float4* wr = reinterpret_cast<const float4*>(W  + d * FEAT);

    float s = 0.f;
#pragma unroll
    for (int f = lane; f < FEAT / 4; f += 32) {
        float4 a = fr[f];
        float4 c = wr[f];
        s += a.x * c.x + a.y * c.y + a.z * c.z + a.w * c.w;
    }

#pragma unroll
    for (int o = 16; o > 0; o >>= 1)
        s += __shfl_down_sync(0xffffffffu, s, o);

    if (lane == 0)
        g_P[d * VOCAB + v] = s + bias[d];
}

// ---------------------------------------------------------------------------
// Kernel 2: gather/scatter. out[(b*DIM + d)*SEQ + l] = P[d][idx[b][l]]
// One block per (b, 256-token chunk). Each thread owns one float4 slot
// (lq = tid & 63, fixed) across 16 d-rows (d = tid>>6 + 4k). Its 4 indices
// are loop-invariant -> ONE coalesced int4 global load. sP is [d][v] so a
// warp (fixed d) gathers from <=10 consecutive words -> conflict-free.
// Fully unrolled: 64 independent LDS + 16 independent STG.128 per thread.
// ---------------------------------------------------------------------------
__global__ void __launch_bounds__(THREADS, 4)
gather_kernel(const int* __restrict__ idx, float* __restrict__ out) {
    __shared__ float sP[DIM * VOCAB];

    const int b   = blockIdx.y;
    const int l0  = blockIdx.x * CHUNK;
    const int tid = threadIdx.x;
    const int lq  = tid & 63;            // float4 slot within chunk (fixed)
    const int db  = tid >> 6;            // base d-row (0..3)

    // This thread's 4 vocab indices (coalesced 16B load, values 0..9)
    int4 iv = *reinterpret_cast<const int4*>(idx + b * SEQ + l0 + lq * 4);

    // Projected table into shared
    for (int i = tid; i < DIM * VOCAB; i += THREADS)
        sP[i] = g_P[i];
    __syncthreads();

    float* ob = out + (b * DIM) * SEQ + l0 + lq * 4;

#pragma unroll
    for (int k = 0; k < ITERS; k++) {
        const int d = db + 4 * k;
        const float* p = &sP[d * VOCAB];

        float4 r;
        r.x = p[iv.x];
        r.y = p[iv.y];
        r.z = p[iv.z];
        r.w = p[iv.w];

        *reinterpret_cast<float4*>(ob + d * SEQ) = r;
    }
}

// ---------------------------------------------------------------------------
// Launch: two kernels on the same stream (graph-capturable, no allocs).
// Inputs per metadata order: indices (int32), fp_table (f32), W (f32), b (f32)
// ---------------------------------------------------------------------------
extern "C" void kernel_launch(void* const* d_in, const int* in_sizes, int n_in,
                              void* d_out, int out_size) {
    const int*   idx  = (const int*)d_in[0];
    const float* fp   = (const float*)d_in[1];
    const float* W    = (const float*)d_in[2];
    const float* bias = (const float*)d_in[3];
    float*       out  = (float*)d_out;

    // 640 warps -> 80 blocks of 256 threads
    compute_P_kernel<<<80, 256>>>(fp, W, bias);

    dim3 grid(SEQ / CHUNK, BATCH);            // (16, 32) = 512 blocks, 1 wave
    gather_kernel<<<grid, THREADS>>>(idx, out);
}

// round 5
// speedup vs baseline: 1.0251x; 1.0201x over previous
#include <cuda_runtime.h>
#include <stdint.h>

// Shapes (fixed by the problem)
#define BATCH 32
#define SEQ   4096
#define VOCAB 10
#define FEAT  1024
#define DIM   64

#define CHUNK     256                 // tokens per inner chunk
#define THREADS   256
#define CPB       4                   // chunks per block
#define GBLOCKS   (BATCH * (SEQ / CHUNK) / CPB)   // 128 CTAs -> ~1 per SM

// Precomputed projected table: P[d][v] = b[d] + sum_f fp[v][f] * W[d][f]
__device__ float g_P[DIM * VOCAB];

// ---------------------------------------------------------------------------
// Kernel 1: tiny 10x64x1024 GEMM. One warp per (d, v) pair -> 640 warps.
// ---------------------------------------------------------------------------
__global__ void compute_P_kernel(const float* __restrict__ fp,
                                 const float* __restrict__ W,
                                 const float* __restrict__ bias) {
    int w    = (blockIdx.x * blockDim.x + threadIdx.x) >> 5;
    int lane = threadIdx.x & 31;
    if (w >= DIM * VOCAB) return;
    int d = w / VOCAB;
    int v = w - d * VOCAB;

    const float4* fr = reinterpret_cast<const float4*>(fp + v * FEAT);
    const float4* wr = reinterpret_cast<const float4*>(W  + d * FEAT);

    float s = 0.f;
#pragma unroll
    for (int f = lane; f < FEAT / 4; f += 32) {
        float4 a = fr[f];
        float4 c = wr[f];
        s += a.x * c.x + a.y * c.y + a.z * c.z + a.w * c.w;
    }

#pragma unroll
    for (int o = 16; o > 0; o >>= 1)
        s += __shfl_down_sync(0xffffffffu, s, o);

    if (lane == 0)
        g_P[d * VOCAB + v] = s + bias[d];
}

// ---------------------------------------------------------------------------
// Kernel 2: gather. out[(b*DIM + d)*SEQ + l] = P[d][idx[b][l]]
// 128 CTAs (~1/SM), each owns 4 consecutive 256-token chunks of one batch
// row. sP loaded ONCE per CTA. Next chunk's index int4 prefetched before the
// current chunk's stores (software pipeline) -> no front-batched LDG pile-up
// (avoids the B300 multi-CTA L1tex-queue spread). Per chunk per thread:
// fixed float4 slot lq, 16 d-rows -> 64 conflict-free LDS + 16 STG.128.
// ---------------------------------------------------------------------------
__global__ void __launch_bounds__(THREADS)
gather_kernel(const int* __restrict__ idx, float* __restrict__ out) {
    __shared__ float sP[DIM * VOCAB];

    const int tid = threadIdx.x;
    const int lq  = tid & 63;            // float4 slot within chunk (fixed)
    const int db  = tid >> 6;            // base d-row (0..3)

    // Block -> 4 consecutive chunks of one batch row
    const int cid0 = blockIdx.x * CPB;               // global chunk id
    const int b    = cid0 >> 4;                      // 16 chunks per b
    const int l0   = (cid0 & 15) * CHUNK;            // token offset in row b

    const int*  ib = idx + b * SEQ + l0 + lq * 4;
    float*      ob = out + (b * DIM) * SEQ + l0 + lq * 4;

    // Prefetch chunk 0 indices, then load table
    int4 iv = *reinterpret_cast<const int4*>(ib);

    for (int i = tid; i < DIM * VOCAB; i += THREADS)
        sP[i] = g_P[i];
    __syncthreads();

#pragma unroll
    for (int c = 0; c < CPB; c++) {
        // Prefetch next chunk's indices before issuing this chunk's stores
        int4 nv = iv;
        if (c + 1 < CPB)
            nv = *reinterpret_cast<const int4*>(ib + (c + 1) * CHUNK);

        float* oc = ob + c * CHUNK;
#pragma unroll
        for (int k = 0; k < 16; k++) {
            const int d = db + 4 * k;
            const float* p = &sP[d * VOCAB];
            float4 r;
            r.x = p[iv.x];
            r.y = p[iv.y];
            r.z = p[iv.z];
            r.w = p[iv.w];
            *reinterpret_cast<float4*>(oc + d * SEQ) = r;
        }
        iv = nv;
    }
}

// ---------------------------------------------------------------------------
// Inputs per metadata order: indices (int32), fp_table (f32), W (f32), b (f32)
// ---------------------------------------------------------------------------
extern "C" void kernel_launch(void* const* d_in, const int* in_sizes, int n_in,
                              void* d_out, int out_size) {
    const int*   idx  = (const int*)d_in[0];
    const float* fp   = (const float*)d_in[1];
    const float* W    = (const float*)d_in[2];
    const float* bias = (const float*)d_in[3];
    float*       out  = (float*)d_out;

    compute_P_kernel<<<80, 256>>>(fp, W, bias);
    gather_kernel<<<GBLOCKS, THREADS>>>(idx, out);   // 128 CTAs
}